// round 12
// baseline (speedup 1.0000x reference)
#include <cuda_runtime.h>

// 2-layer GCN, scatter form, project-on-the-small-side:
//   layer1: aggregate xs = x*dinv (3-dim, padded to 4) over edges, THEN apply W1.
//   layer2: project m = (v@W2)*dinv (3-dim, padded to 4), THEN aggregate.
// Self loops via acc init. 1 edge/thread at B=256 (measured best; R8 batching and
// B=512 both regress). Gather + index loads via __ldg to force the .NC path
// (matches R5's measured-best SASS). g_cnt self-resets in prep1.
// Scatters sit at the joint L1tex-wavefront / L2-sector floor (~2 wf + ~2 sectors/edge).

#define NMAX 200000

__device__ int    g_cnt [NMAX];   // zero-initialized at module load
__device__ float  g_dinv[NMAX];
__device__ float4 g_xs  [NMAX];   // x*dinv padded
__device__ float4 g_acc1[NMAX];   // layer1 aggregate
__device__ float4 g_m2  [NMAX];   // (v@W2)*dinv padded
__device__ float4 g_acc2[NMAX];   // layer2 aggregate

__device__ __forceinline__ void red_v4(float* p, float4 v) {
    asm volatile("red.global.add.v4.f32 [%0], {%1, %2, %3, %4};"
                 :: "l"(p), "f"(v.x), "f"(v.y), "f"(v.z), "f"(v.w)
                 : "memory");
}

__global__ void k_hist(const int* __restrict__ dst, int E) {
    int e = blockIdx.x * blockDim.x + threadIdx.x;
    if (e < E) atomicAdd(&g_cnt[__ldg(&dst[e])], 1);
}

// dinv, xs = x*dinv (pad 0), acc1 = xs (self loop); reset cnt for next replay
__global__ void k_prep1(const float* __restrict__ x, int n) {
    int i = blockIdx.x * blockDim.x + threadIdx.x;
    if (i >= n) return;
    int c = g_cnt[i];
    g_cnt[i] = 0;                       // ready for next graph replay
    float dv = rsqrtf((float)c + 1.0f);
    g_dinv[i] = dv;
    float4 v;
    v.x = x[i * 3 + 0] * dv;
    v.y = x[i * 3 + 1] * dv;
    v.z = x[i * 3 + 2] * dv;
    v.w = 0.0f;
    g_xs[i]   = v;
    g_acc1[i] = v;
}

// 1 thread/edge: 16B NC gather + 16B vector reduction.
// LAYER selects device-global arrays (resolved in device code).
template <int LAYER>
__global__ void k_scatter(const int* __restrict__ src,
                          const int* __restrict__ dst, int E) {
    const float4* msg = (LAYER == 1) ? g_xs  : g_m2;
    float4*       acc = (LAYER == 1) ? g_acc1 : g_acc2;
    int e = blockIdx.x * blockDim.x + threadIdx.x;
    if (e >= E) return;
    int s = __ldg(&src[e]);
    int d = __ldg(&dst[e]);
    float4 v = __ldg(&msg[s]);          // LDG.E.NC.128
    red_v4((float*)&acc[d], v);
}

// v = relu(dv*(acc1@W1)+b1);  m2 = (v@W2)*dv;  acc2 = m2 (self loop)
__global__ void k_prep2(const float* __restrict__ W1,
                        const float* __restrict__ b1,
                        const float* __restrict__ W2, int n) {
    int i = blockIdx.x * blockDim.x + threadIdx.x;
    if (i >= n) return;
    float dv = g_dinv[i];
    float4 a = g_acc1[i];
    float h0 = 0.0f, h1 = 0.0f, h2 = 0.0f;
#pragma unroll
    for (int f = 0; f < 16; f++) {
        float h = a.x * __ldg(&W1[f]) + a.y * __ldg(&W1[16 + f]) + a.z * __ldg(&W1[32 + f]);
        float v = fmaxf(h * dv + __ldg(&b1[f]), 0.0f);
        h0 += v * __ldg(&W2[f * 3 + 0]);
        h1 += v * __ldg(&W2[f * 3 + 1]);
        h2 += v * __ldg(&W2[f * 3 + 2]);
    }
    float4 m;
    m.x = h0 * dv; m.y = h1 * dv; m.z = h2 * dv; m.w = 0.0f;
    g_m2[i]   = m;
    g_acc2[i] = m;
}

// 3N threads; thread i writes out[i] — fully coalesced stores.
__global__ void k_final(const float* __restrict__ b2,
                        float* __restrict__ out, int n3) {
    int i = blockIdx.x * blockDim.x + threadIdx.x;
    if (i >= n3) return;
    int node = i / 3;
    int c = i - node * 3;
    const float* a = (const float*)&g_acc2[node];
    out[i] = a[c] * g_dinv[node] + __ldg(&b2[c]);
}

extern "C" void kernel_launch(void* const* d_in, const int* in_sizes, int n_in,
                              void* d_out, int out_size) {
    const float* x  = (const float*)d_in[0];
    const int*   ei = (const int*)  d_in[1];
    const float* W1 = (const float*)d_in[2];
    const float* b1 = (const float*)d_in[3];
    const float* W2 = (const float*)d_in[4];
    const float* b2 = (const float*)d_in[5];
    float* out = (float*)d_out;

    int n = in_sizes[0] / 3;
    int E = in_sizes[1] / 2;
    const int* src = ei;
    const int* dst = ei + E;

    const int B = 256;
    int gn = (n + B - 1) / B;
    int ge = (E + B - 1) / B;
    int gf = (n * 3 + B - 1) / B;

    k_hist<<<ge, B>>>(dst, E);
    k_prep1<<<gn, B>>>(x, n);
    k_scatter<1><<<ge, B>>>(src, dst, E);
    k_prep2<<<gn, B>>>(W1, b1, W2, n);
    k_scatter<2><<<ge, B>>>(src, dst, E);
    k_final<<<gf, B>>>(b2, out, n * 3);
}

// round 13
// speedup vs baseline: 1.0312x; 1.0312x over previous
#include <cuda_runtime.h>

// 2-layer GCN, scatter form, with "project-on-the-small-side" trick:
//   layer1: aggregate xs = x*dinv (3-dim, padded to 4) over edges, THEN apply W1.
//   layer2: project m = (v@W2)*dinv (3-dim, padded to 4), THEN aggregate.
// Self loops handled by initializing acc = own message.
// This is the best-measured configuration (R5: 142.1us). All later variants
// (edge batching, B=512, templated scatter, __ldg NC hints, zero_cnt removal)
// measured equal or worse; scatters sit at the joint L1tex-wavefront /
// L2-sector floor (~2 wavefronts + ~2 sectors per edge, irreducible).

#define NMAX 200000

__device__ int   g_cnt [NMAX];
__device__ float g_dinv[NMAX];
__device__ float4 g_xs  [NMAX];   // x*dinv padded
__device__ float4 g_acc1[NMAX];   // layer1 aggregate
__device__ float4 g_m2  [NMAX];   // (v@W2)*dinv padded
__device__ float4 g_acc2[NMAX];   // layer2 aggregate

__global__ void k_zero_cnt(int n) {
    int i = blockIdx.x * blockDim.x + threadIdx.x;
    if (i < n) g_cnt[i] = 0;
}

__global__ void k_hist(const int* __restrict__ dst, int E) {
    int e = blockIdx.x * blockDim.x + threadIdx.x;
    if (e < E) atomicAdd(&g_cnt[dst[e]], 1);
}

// dinv, xs = x*dinv (pad 0), acc1 = xs (self loop)
__global__ void k_prep1(const float* __restrict__ x, int n) {
    int i = blockIdx.x * blockDim.x + threadIdx.x;
    if (i >= n) return;
    float dv = rsqrtf((float)g_cnt[i] + 1.0f);
    g_dinv[i] = dv;
    float4 v;
    v.x = x[i * 3 + 0] * dv;
    v.y = x[i * 3 + 1] * dv;
    v.z = x[i * 3 + 2] * dv;
    v.w = 0.0f;
    g_xs[i]   = v;
    g_acc1[i] = v;
}

// 1 thread/edge: 16B gather + 16B vector reduction
__global__ void k_scatter1(const int* __restrict__ src,
                           const int* __restrict__ dst, int E) {
    int e = blockIdx.x * blockDim.x + threadIdx.x;
    if (e >= E) return;
    int s = src[e], d = dst[e];
    float4 v = g_xs[s];
    float* p = (float*)&g_acc1[d];
    asm volatile("red.global.add.v4.f32 [%0], {%1, %2, %3, %4};"
                 :: "l"(p), "f"(v.x), "f"(v.y), "f"(v.z), "f"(v.w)
                 : "memory");
}

// v = relu(dv*(acc1@W1)+b1);  m2 = (v@W2)*dv;  acc2 = m2 (self loop)
__global__ void k_prep2(const float* __restrict__ W1,
                        const float* __restrict__ b1,
                        const float* __restrict__ W2, int n) {
    int i = blockIdx.x * blockDim.x + threadIdx.x;
    if (i >= n) return;
    float dv = g_dinv[i];
    float4 a = g_acc1[i];
    float h0 = 0.0f, h1 = 0.0f, h2 = 0.0f;
#pragma unroll
    for (int f = 0; f < 16; f++) {
        float h = a.x * __ldg(&W1[f]) + a.y * __ldg(&W1[16 + f]) + a.z * __ldg(&W1[32 + f]);
        float v = fmaxf(h * dv + __ldg(&b1[f]), 0.0f);
        h0 += v * __ldg(&W2[f * 3 + 0]);
        h1 += v * __ldg(&W2[f * 3 + 1]);
        h2 += v * __ldg(&W2[f * 3 + 2]);
    }
    float4 m;
    m.x = h0 * dv; m.y = h1 * dv; m.z = h2 * dv; m.w = 0.0f;
    g_m2[i]   = m;
    g_acc2[i] = m;
}

__global__ void k_scatter2(const int* __restrict__ src,
                           const int* __restrict__ dst, int E) {
    int e = blockIdx.x * blockDim.x + threadIdx.x;
    if (e >= E) return;
    int s = src[e], d = dst[e];
    float4 v = g_m2[s];
    float* p = (float*)&g_acc2[d];
    asm volatile("red.global.add.v4.f32 [%0], {%1, %2, %3, %4};"
                 :: "l"(p), "f"(v.x), "f"(v.y), "f"(v.z), "f"(v.w)
                 : "memory");
}

__global__ void k_final(const float* __restrict__ b2,
                        float* __restrict__ out, int n) {
    int i = blockIdx.x * blockDim.x + threadIdx.x;
    if (i >= n) return;
    float dv = g_dinv[i];
    float4 a = g_acc2[i];
    out[i * 3 + 0] = a.x * dv + __ldg(&b2[0]);
    out[i * 3 + 1] = a.y * dv + __ldg(&b2[1]);
    out[i * 3 + 2] = a.z * dv + __ldg(&b2[2]);
}

extern "C" void kernel_launch(void* const* d_in, const int* in_sizes, int n_in,
                              void* d_out, int out_size) {
    const float* x  = (const float*)d_in[0];
    const int*   ei = (const int*)  d_in[1];
    const float* W1 = (const float*)d_in[2];
    const float* b1 = (const float*)d_in[3];
    const float* W2 = (const float*)d_in[4];
    const float* b2 = (const float*)d_in[5];
    float* out = (float*)d_out;

    int n = in_sizes[0] / 3;
    int E = in_sizes[1] / 2;
    const int* src = ei;
    const int* dst = ei + E;

    const int B = 256;
    int gn = (n + B - 1) / B;
    int ge = (E + B - 1) / B;

    k_zero_cnt<<<gn, B>>>(n);
    k_hist<<<ge, B>>>(dst, E);
    k_prep1<<<gn, B>>>(x, n);
    k_scatter1<<<ge, B>>>(src, dst, E);
    k_prep2<<<gn, B>>>(W1, b1, W2, n);
    k_scatter2<<<ge, B>>>(src, dst, E);
    k_final<<<gn, B>>>(b2, out, n);
}

// round 15
// speedup vs baseline: 1.0431x; 1.0115x over previous
#include <cuda_runtime.h>

// 2-layer GCN, scatter form, "project-on-the-small-side":
//   layer1: aggregate xs = x*dinv (3-dim, padded to 4) over edges, THEN apply W1.
//   layer2: project m = (v@W2)*dinv (3-dim, padded to 4), THEN aggregate.
// Self loops via acc init. FINAL configuration — measured floor.
//
// Floor accounting (sm_103a, measured over R3-R13):
//   cost invariant = 5 random L2 lines per edge:
//     hist RED(1) + gather+RED(2) + gather+RED(2).
//   CSR-pull alternative is also 5 lines/edge (place 2 + hist 1 + pulls 2) — R4
//   measured it 120us slower due to build overhead. Edge batching (R8) regresses
//   via cross-CTA L1tex-queue contention. B=512, __ldg NC hints: neutral/worse.
//   Scatters run at ~80% L2 / ~76% L1tex simultaneously; 142-144us total.

#define NMAX 200000

__device__ int   g_cnt [NMAX];
__device__ float g_dinv[NMAX];
__device__ float4 g_xs  [NMAX];   // x*dinv padded
__device__ float4 g_acc1[NMAX];   // layer1 aggregate
__device__ float4 g_m2  [NMAX];   // (v@W2)*dinv padded
__device__ float4 g_acc2[NMAX];   // layer2 aggregate

__global__ void k_zero_cnt(int n) {
    int i = blockIdx.x * blockDim.x + threadIdx.x;
    if (i < n) g_cnt[i] = 0;
}

__global__ void k_hist(const int* __restrict__ dst, int E) {
    int e = blockIdx.x * blockDim.x + threadIdx.x;
    if (e < E) atomicAdd(&g_cnt[dst[e]], 1);
}

// dinv, xs = x*dinv (pad 0), acc1 = xs (self loop)
__global__ void k_prep1(const float* __restrict__ x, int n) {
    int i = blockIdx.x * blockDim.x + threadIdx.x;
    if (i >= n) return;
    float dv = rsqrtf((float)g_cnt[i] + 1.0f);
    g_dinv[i] = dv;
    float4 v;
    v.x = x[i * 3 + 0] * dv;
    v.y = x[i * 3 + 1] * dv;
    v.z = x[i * 3 + 2] * dv;
    v.w = 0.0f;
    g_xs[i]   = v;
    g_acc1[i] = v;
}

// 1 thread/edge: 16B gather + 16B vector reduction
__global__ void k_scatter1(const int* __restrict__ src,
                           const int* __restrict__ dst, int E) {
    int e = blockIdx.x * blockDim.x + threadIdx.x;
    if (e >= E) return;
    int s = src[e], d = dst[e];
    float4 v = g_xs[s];
    float* p = (float*)&g_acc1[d];
    asm volatile("red.global.add.v4.f32 [%0], {%1, %2, %3, %4};"
                 :: "l"(p), "f"(v.x), "f"(v.y), "f"(v.z), "f"(v.w)
                 : "memory");
}

// v = relu(dv*(acc1@W1)+b1);  m2 = (v@W2)*dv;  acc2 = m2 (self loop)
__global__ void k_prep2(const float* __restrict__ W1,
                        const float* __restrict__ b1,
                        const float* __restrict__ W2, int n) {
    int i = blockIdx.x * blockDim.x + threadIdx.x;
    if (i >= n) return;
    float dv = g_dinv[i];
    float4 a = g_acc1[i];
    float h0 = 0.0f, h1 = 0.0f, h2 = 0.0f;
#pragma unroll
    for (int f = 0; f < 16; f++) {
        float h = a.x * __ldg(&W1[f]) + a.y * __ldg(&W1[16 + f]) + a.z * __ldg(&W1[32 + f]);
        float v = fmaxf(h * dv + __ldg(&b1[f]), 0.0f);
        h0 += v * __ldg(&W2[f * 3 + 0]);
        h1 += v * __ldg(&W2[f * 3 + 1]);
        h2 += v * __ldg(&W2[f * 3 + 2]);
    }
    float4 m;
    m.x = h0 * dv; m.y = h1 * dv; m.z = h2 * dv; m.w = 0.0f;
    g_m2[i]   = m;
    g_acc2[i] = m;
}

__global__ void k_scatter2(const int* __restrict__ src,
                           const int* __restrict__ dst, int E) {
    int e = blockIdx.x * blockDim.x + threadIdx.x;
    if (e >= E) return;
    int s = src[e], d = dst[e];
    float4 v = g_m2[s];
    float* p = (float*)&g_acc2[d];
    asm volatile("red.global.add.v4.f32 [%0], {%1, %2, %3, %4};"
                 :: "l"(p), "f"(v.x), "f"(v.y), "f"(v.z), "f"(v.w)
                 : "memory");
}

__global__ void k_final(const float* __restrict__ b2,
                        float* __restrict__ out, int n) {
    int i = blockIdx.x * blockDim.x + threadIdx.x;
    if (i >= n) return;
    float dv = g_dinv[i];
    float4 a = g_acc2[i];
    out[i * 3 + 0] = a.x * dv + __ldg(&b2[0]);
    out[i * 3 + 1] = a.y * dv + __ldg(&b2[1]);
    out[i * 3 + 2] = a.z * dv + __ldg(&b2[2]);
}

extern "C" void kernel_launch(void* const* d_in, const int* in_sizes, int n_in,
                              void* d_out, int out_size) {
    const float* x  = (const float*)d_in[0];
    const int*   ei = (const int*)  d_in[1];
    const float* W1 = (const float*)d_in[2];
    const float* b1 = (const float*)d_in[3];
    const float* W2 = (const float*)d_in[4];
    const float* b2 = (const float*)d_in[5];
    float* out = (float*)d_out;

    int n = in_sizes[0] / 3;
    int E = in_sizes[1] / 2;
    const int* src = ei;
    const int* dst = ei + E;

    const int B = 256;
    int gn = (n + B - 1) / B;
    int ge = (E + B - 1) / B;

    k_zero_cnt<<<gn, B>>>(n);
    k_hist<<<ge, B>>>(dst, E);
    k_prep1<<<gn, B>>>(x, n);
    k_scatter1<<<ge, B>>>(src, dst, E);
    k_prep2<<<gn, B>>>(W1, b1, W2, n);
    k_scatter2<<<ge, B>>>(src, dst, E);
    k_final<<<gn, B>>>(b2, out, n);
}